// round 1
// baseline (speedup 1.0000x reference)
#include <cuda_runtime.h>
#include <cuda_bf16.h>

// CenterLoss, B=1024, C=100000, F=128.
// loss = ( sum_b clip(||x_b - centers[labels_b]||^2, 1e-12, 1e12)
//          + (B*C - B)*1e-12 ) / B
// The one-hot mask + clip means the full [B,C] distmat is never needed.

#define BATCH     1024
#define FEAT      128
#define NBLOCKS   128          // 8 warps/block * 128 blocks = 1024 warps = 1 warp per row
#define WARPS_PER_BLOCK 8
// (B*C - B) * 1e-12 = 1024*99999*1e-12
#define MASK_CONST 1.02398976e-4f

__device__ float g_partials[NBLOCKS];

__global__ __launch_bounds__(WARPS_PER_BLOCK * 32)
void centerloss_rows(const float* __restrict__ x,
                     const int*   __restrict__ labels,
                     const float* __restrict__ centers) {
    const int warp = threadIdx.x >> 5;
    const int lane = threadIdx.x & 31;
    const int row  = blockIdx.x * WARPS_PER_BLOCK + warp;   // 0..1023

    // Each lane handles one float4 (4 floats) of the 128-dim row.
    const float4* xr = reinterpret_cast<const float4*>(x + (size_t)row * FEAT);
    const int lbl = labels[row];
    const float4* cr = reinterpret_cast<const float4*>(centers + (size_t)lbl * FEAT);

    float4 a = xr[lane];
    float4 c = cr[lane];
    float dx = a.x - c.x, dy = a.y - c.y, dz = a.z - c.z, dw = a.w - c.w;
    float d = dx * dx + dy * dy + dz * dz + dw * dw;

    // warp tree reduce (deterministic)
    #pragma unroll
    for (int o = 16; o > 0; o >>= 1)
        d += __shfl_xor_sync(0xFFFFFFFFu, d, o);

    __shared__ float warp_sums[WARPS_PER_BLOCK];
    if (lane == 0) {
        // clamp the per-row distance exactly as the reference's clip does
        warp_sums[warp] = fminf(fmaxf(d, 1e-12f), 1e12f);
    }
    __syncthreads();

    if (threadIdx.x == 0) {
        float s = 0.0f;
        #pragma unroll
        for (int w = 0; w < WARPS_PER_BLOCK; w++) s += warp_sums[w];
        g_partials[blockIdx.x] = s;
    }
}

__global__ __launch_bounds__(NBLOCKS)
void centerloss_finalize(float* __restrict__ out) {
    const int tid = threadIdx.x;      // 0..127
    float v = g_partials[tid];

    // deterministic block reduce: 4 warps -> shared -> warp 0
    #pragma unroll
    for (int o = 16; o > 0; o >>= 1)
        v += __shfl_xor_sync(0xFFFFFFFFu, v, o);

    __shared__ float ws[4];
    if ((tid & 31) == 0) ws[tid >> 5] = v;
    __syncthreads();

    if (tid == 0) {
        float total = ws[0] + ws[1] + ws[2] + ws[3];
        out[0] = (total + MASK_CONST) / (float)BATCH;
    }
}

extern "C" void kernel_launch(void* const* d_in, const int* in_sizes, int n_in,
                              void* d_out, int out_size) {
    const float* x       = (const float*)d_in[0];   // [1024, 128] f32
    const int*   labels  = (const int*)  d_in[1];   // [1024] i32
    const float* centers = (const float*)d_in[2];   // [100000, 128] f32
    float* out = (float*)d_out;

    centerloss_rows<<<NBLOCKS, WARPS_PER_BLOCK * 32>>>(x, labels, centers);
    centerloss_finalize<<<1, NBLOCKS>>>(out);
}